// round 2
// baseline (speedup 1.0000x reference)
#include <cuda_runtime.h>
#include <math.h>

#define B_ 2
#define N_ 2048
#define E_ 1024
#define H_ 16
#define D_ 64
#define THREE_E 3072
#define M_ROWS 4096   // B*N

// Scratch (allocation-free rule: __device__ globals)
__device__ float g_qkv[(size_t)M_ROWS * THREE_E];   // [B,N,3E] ~50 MB
__device__ float g_attn[(size_t)M_ROWS * E_];       // [B,N,E]  ~17 MB

// ---------------------------------------------------------------------------
// SGEMM: C[M,Nc] = A[M,K] @ W[K,Nc] + bias[Nc]
// 128x128 tile, BK=8, 256 threads, 8x8 per thread.
// ---------------------------------------------------------------------------
__global__ void __launch_bounds__(256)
sgemm_bias(const float* __restrict__ A,
           const float* __restrict__ W,
           const float* __restrict__ bias,
           float* __restrict__ C,
           int M, int Nc, int K)
{
    __shared__ float As[8][128];   // transposed A tile
    __shared__ float Bs[8][128];

    const int tid = threadIdx.x;
    const int tx = tid & 15;       // 0..15
    const int ty = tid >> 4;       // 0..15
    const int m0 = blockIdx.y * 128;
    const int n0 = blockIdx.x * 128;

    float acc[8][8];
#pragma unroll
    for (int i = 0; i < 8; i++)
#pragma unroll
        for (int j = 0; j < 8; j++) acc[i][j] = 0.f;

    const int arow = tid >> 1;         // 0..127
    const int acol = (tid & 1) * 4;    // 0 or 4
    const int brow = tid >> 5;         // 0..7
    const int bcol = (tid & 31) * 4;   // 0..124

    for (int k0 = 0; k0 < K; k0 += 8) {
        float4 av = *(const float4*)&A[(size_t)(m0 + arow) * K + k0 + acol];
        float4 bv = *(const float4*)&W[(size_t)(k0 + brow) * Nc + n0 + bcol];
        __syncthreads();
        As[acol + 0][arow] = av.x;
        As[acol + 1][arow] = av.y;
        As[acol + 2][arow] = av.z;
        As[acol + 3][arow] = av.w;
        *(float4*)&Bs[brow][bcol] = bv;
        __syncthreads();
#pragma unroll
        for (int kk = 0; kk < 8; kk++) {
            float4 a0 = *(const float4*)&As[kk][ty * 8];
            float4 a1 = *(const float4*)&As[kk][ty * 8 + 4];
            float4 b0 = *(const float4*)&Bs[kk][tx * 8];
            float4 b1 = *(const float4*)&Bs[kk][tx * 8 + 4];
            float a[8] = {a0.x, a0.y, a0.z, a0.w, a1.x, a1.y, a1.z, a1.w};
            float b[8] = {b0.x, b0.y, b0.z, b0.w, b1.x, b1.y, b1.z, b1.w};
#pragma unroll
            for (int i = 0; i < 8; i++)
#pragma unroll
                for (int j = 0; j < 8; j++)
                    acc[i][j] = fmaf(a[i], b[j], acc[i][j]);
        }
    }

#pragma unroll
    for (int i = 0; i < 8; i++) {
        size_t row = (size_t)(m0 + ty * 8 + i) * Nc + n0;
#pragma unroll
        for (int j4 = 0; j4 < 2; j4++) {
            int jc = tx * 8 + j4 * 4;
            float4 bz = *(const float4*)&bias[n0 + jc];
            float4 out;
            out.x = acc[i][j4 * 4 + 0] + bz.x;
            out.y = acc[i][j4 * 4 + 1] + bz.y;
            out.z = acc[i][j4 * 4 + 2] + bz.z;
            out.w = acc[i][j4 * 4 + 3] + bz.w;
            *(float4*)&C[row + jc] = out;
        }
    }
}

// ---------------------------------------------------------------------------
// Fused flash-style attention.
// Grid: (N/64, H, B). Block: 16x16 = 256 threads.
// Each block: 64 queries x D=64. Streams K tiles then V tiles through one
// smem buffer; online softmax; accumulates O in registers (4x4 per thread).
// ---------------------------------------------------------------------------
#define LDS_ 65   // smem row stride (conflict-reducing padding)

__global__ void __launch_bounds__(256)
attn_kernel(const float* __restrict__ qkv, float* __restrict__ attn_out)
{
    extern __shared__ float sm[];
    float* Qs  = sm;                   // [64][LDS_]
    float* KVs = sm + 64 * LDS_;       // [64][LDS_]
    float* Ss  = sm + 2 * 64 * LDS_;   // [64][LDS_]

    const int tx = threadIdx.x;        // 0..15 (cols)
    const int ty = threadIdx.y;        // 0..15 (rows)
    const int tid = ty * 16 + tx;
    const int q0 = blockIdx.x * 64;
    const int h  = blockIdx.y;
    const int b  = blockIdx.z;

    const float scale = 0.125f;        // D^-0.5, D=64
    const size_t base = (size_t)b * N_ * THREE_E;
    const int hoff = h * D_;

    // Load Q tile (coalesced: consecutive tid -> consecutive d)
    for (int i = tid; i < 64 * 64; i += 256) {
        int r = i >> 6, c = i & 63;
        Qs[r * LDS_ + c] = qkv[base + (size_t)(q0 + r) * THREE_E + hoff + c];
    }

    float o[4][4];
    float m_r[4], l_r[4];
#pragma unroll
    for (int i = 0; i < 4; i++) {
        m_r[i] = -1e30f;
        l_r[i] = 0.f;
#pragma unroll
        for (int j = 0; j < 4; j++) o[i][j] = 0.f;
    }

    for (int kt = 0; kt < N_ / 64; kt++) {
        const int k0 = kt * 64;
        __syncthreads();   // previous O-update finished reading KVs/Ss
        // Load K tile
        for (int i = tid; i < 64 * 64; i += 256) {
            int r = i >> 6, c = i & 63;
            KVs[r * LDS_ + c] =
                qkv[base + (size_t)(k0 + r) * THREE_E + E_ + hoff + c];
        }
        __syncthreads();

        // S = scale * Q K^T  (4x4 per thread)
        float s[4][4];
#pragma unroll
        for (int i = 0; i < 4; i++)
#pragma unroll
            for (int j = 0; j < 4; j++) s[i][j] = 0.f;
#pragma unroll 4
        for (int d = 0; d < 64; d++) {
            float a[4], bb[4];
#pragma unroll
            for (int i = 0; i < 4; i++) a[i]  = Qs[(ty * 4 + i) * LDS_ + d];
#pragma unroll
            for (int j = 0; j < 4; j++) bb[j] = KVs[(tx * 4 + j) * LDS_ + d];
#pragma unroll
            for (int i = 0; i < 4; i++)
#pragma unroll
                for (int j = 0; j < 4; j++)
                    s[i][j] = fmaf(a[i], bb[j], s[i][j]);
        }

        // Online softmax update (rows owned by ty-group; reduce across 16 tx lanes)
#pragma unroll
        for (int i = 0; i < 4; i++) {
            float rmax = -1e30f;
#pragma unroll
            for (int j = 0; j < 4; j++) {
                s[i][j] *= scale;
                rmax = fmaxf(rmax, s[i][j]);
            }
#pragma unroll
            for (int off = 8; off > 0; off >>= 1)
                rmax = fmaxf(rmax, __shfl_xor_sync(0xffffffffu, rmax, off, 16));

            float newm = fmaxf(m_r[i], rmax);
            float alpha = __expf(m_r[i] - newm);
            m_r[i] = newm;

            float rsum = 0.f;
#pragma unroll
            for (int j = 0; j < 4; j++) {
                s[i][j] = __expf(s[i][j] - newm);
                rsum += s[i][j];
            }
#pragma unroll
            for (int off = 8; off > 0; off >>= 1)
                rsum += __shfl_xor_sync(0xffffffffu, rsum, off, 16);

            l_r[i] = l_r[i] * alpha + rsum;
#pragma unroll
            for (int j = 0; j < 4; j++) o[i][j] *= alpha;
        }
        __syncthreads();   // everyone done reading K tile

        // Store P, load V tile (into the same KVs buffer)
#pragma unroll
        for (int i = 0; i < 4; i++)
#pragma unroll
            for (int j = 0; j < 4; j++)
                Ss[(ty * 4 + i) * LDS_ + tx * 4 + j] = s[i][j];
        for (int i = tid; i < 64 * 64; i += 256) {
            int r = i >> 6, c = i & 63;
            KVs[r * LDS_ + c] =
                qkv[base + (size_t)(k0 + r) * THREE_E + 2 * E_ + hoff + c];
        }
        __syncthreads();

        // O += P @ V
#pragma unroll 4
        for (int kk = 0; kk < 64; kk++) {
            float a[4], bb[4];
#pragma unroll
            for (int i = 0; i < 4; i++) a[i]  = Ss[(ty * 4 + i) * LDS_ + kk];
#pragma unroll
            for (int j = 0; j < 4; j++) bb[j] = KVs[kk * LDS_ + tx * 4 + j];
#pragma unroll
            for (int i = 0; i < 4; i++)
#pragma unroll
                for (int j = 0; j < 4; j++)
                    o[i][j] = fmaf(a[i], bb[j], o[i][j]);
        }
    }

    // Write O / l  -> attn_out[b, n, h*D + d]  (layout [B,N,E])
#pragma unroll
    for (int i = 0; i < 4; i++) {
        float inv_l = 1.0f / l_r[i];
        size_t row = ((size_t)b * N_ + q0 + ty * 4 + i) * E_ + hoff + tx * 4;
#pragma unroll
        for (int j = 0; j < 4; j++)
            attn_out[row + j] = o[i][j] * inv_l;
    }
}

// ---------------------------------------------------------------------------
extern "C" void kernel_launch(void* const* d_in, const int* in_sizes, int n_in,
                              void* d_out, int out_size)
{
    const float* x      = (const float*)d_in[0];
    const float* w_qkv  = (const float*)d_in[1];
    const float* b_qkv  = (const float*)d_in[2];
    const float* w_proj = (const float*)d_in[3];
    const float* b_proj = (const float*)d_in[4];
    float* out = (float*)d_out;

    float *qkv_ptr = nullptr, *attn_ptr = nullptr;
    cudaGetSymbolAddress((void**)&qkv_ptr, g_qkv);
    cudaGetSymbolAddress((void**)&attn_ptr, g_attn);

    const int attn_smem = 3 * 64 * LDS_ * (int)sizeof(float);  // 49920 B
    static bool attr_set = false;
    if (!attr_set) {
        cudaFuncSetAttribute(attn_kernel,
                             cudaFuncAttributeMaxDynamicSharedMemorySize,
                             attn_smem);
        attr_set = true;
    }

    // 1) QKV = x @ w_qkv + b_qkv     [4096,1024] x [1024,3072]
    sgemm_bias<<<dim3(THREE_E / 128, M_ROWS / 128), 256>>>(
        x, w_qkv, b_qkv, qkv_ptr, M_ROWS, THREE_E, E_);

    // 2) Fused attention -> g_attn [B,N,E]
    attn_kernel<<<dim3(N_ / 64, H_, B_), dim3(16, 16), attn_smem>>>(
        qkv_ptr, attn_ptr);

    // 3) out = attn @ w_proj + b_proj   [4096,1024] x [1024,1024]
    sgemm_bias<<<dim3(E_ / 128, M_ROWS / 128), 256>>>(
        attn_ptr, w_proj, b_proj, out, M_ROWS, E_, E_);
}

// round 4
// speedup vs baseline: 1.3193x; 1.3193x over previous
#include <cuda_runtime.h>
#include <cuda_bf16.h>
#include <cstdint>
#include <math.h>

#define B_ 2
#define N_ 2048
#define E_ 1024
#define H_ 16
#define D_ 64
#define THREE_E 3072
#define M_ROWS 4096   // B*N

// ---------------------------------------------------------------------------
// Scratch (__device__ globals; allocation-free rule)
// ---------------------------------------------------------------------------
__device__ float g_qkv[(size_t)M_ROWS * THREE_E];            // 50 MB
__device__ float g_attn[(size_t)M_ROWS * E_];                // 17 MB
__device__ __nv_bfloat16 g_a_hi[(size_t)M_ROWS * E_];        // 8 MB (x, later attn)
__device__ __nv_bfloat16 g_a_lo[(size_t)M_ROWS * E_];
__device__ __nv_bfloat16 g_wq_hi[(size_t)THREE_E * E_];      // 6 MB (w_qkv^T, [Nc,K])
__device__ __nv_bfloat16 g_wq_lo[(size_t)THREE_E * E_];
__device__ __nv_bfloat16 g_wp_hi[(size_t)E_ * E_];           // 2 MB (w_proj^T)
__device__ __nv_bfloat16 g_wp_lo[(size_t)E_ * E_];

// ---------------------------------------------------------------------------
// Warp-level bf16 MMA (sm_80+; valid on plain compute_100)
// D(16x8,f32) += A(16x16,bf16,row) * B(16x8,bf16,col)
// ---------------------------------------------------------------------------
__device__ __forceinline__ void mma16816(float* c, const uint32_t* a, const uint32_t* b) {
    asm volatile(
        "mma.sync.aligned.m16n8k16.row.col.f32.bf16.bf16.f32 "
        "{%0,%1,%2,%3}, {%4,%5,%6,%7}, {%8,%9}, {%0,%1,%2,%3};"
        : "+f"(c[0]), "+f"(c[1]), "+f"(c[2]), "+f"(c[3])
        : "r"(a[0]), "r"(a[1]), "r"(a[2]), "r"(a[3]), "r"(b[0]), "r"(b[1]));
}
__device__ __forceinline__ uint32_t lds_u32(const __nv_bfloat16* p) {
    return *reinterpret_cast<const uint32_t*>(p);
}

// ---------------------------------------------------------------------------
// Prep: elementwise split fp32 -> bf16 hi + lo
// ---------------------------------------------------------------------------
__global__ void split_f32(const float* __restrict__ src,
                          __nv_bfloat16* __restrict__ hi,
                          __nv_bfloat16* __restrict__ lo, int n)
{
    int i = blockIdx.x * blockDim.x + threadIdx.x;
    if (i < n) {
        float x = src[i];
        __nv_bfloat16 h = __float2bfloat16(x);
        hi[i] = h;
        lo[i] = __float2bfloat16(x - __bfloat162float(h));
    }
}

// Prep: W [K, Nc] row-major -> Wt hi/lo [Nc, K] (K contiguous)
__global__ void transpose_split(const float* __restrict__ w,
                                __nv_bfloat16* __restrict__ thi,
                                __nv_bfloat16* __restrict__ tlo,
                                int K, int Nc)
{
    __shared__ float t[32][33];
    int n0 = blockIdx.x * 32, k0 = blockIdx.y * 32;
    int tx = threadIdx.x, ty = threadIdx.y;     // 32 x 8
#pragma unroll
    for (int i = 0; i < 32; i += 8)
        t[ty + i][tx] = w[(size_t)(k0 + ty + i) * Nc + n0 + tx];
    __syncthreads();
#pragma unroll
    for (int i = 0; i < 32; i += 8) {
        float v = t[tx][ty + i];
        __nv_bfloat16 h = __float2bfloat16(v);
        size_t o = (size_t)(n0 + ty + i) * K + k0 + tx;
        thi[o] = h;
        tlo[o] = __float2bfloat16(v - __bfloat162float(h));
    }
}

// ---------------------------------------------------------------------------
// Split-bf16 tensor-core GEMM: C[M,Nc] = A[M,K] @ Wt[Nc,K]^T + bias
// CTA: 128x128 tile, 256 thr = 8 warps (2m x 4n), warp tile 64x32.
// K chunk 64. smem rows padded to 72 bf16 (144 B = 9*16B: aligned, conflict-free).
// ---------------------------------------------------------------------------
#define AS_ 72
#define TILE_ELEMS (128 * AS_)
#define GEMM_SMEM (4 * TILE_ELEMS * 2)   // 73728 B

__device__ __forceinline__ void load_tile(const __nv_bfloat16* __restrict__ src,
                                          int row0, int K, int k0,
                                          __nv_bfloat16* dst, int tid)
{
#pragma unroll
    for (int it = 0; it < 4; it++) {
        int idx = tid + it * 256;          // 0..1023
        int r = idx >> 3, g = idx & 7;     // 128 rows x 8 groups of 8 elems
        uint4 v = *reinterpret_cast<const uint4*>(
            src + (size_t)(row0 + r) * K + k0 + g * 8);
        *reinterpret_cast<uint4*>(dst + r * AS_ + g * 8) = v;
    }
}

__global__ void __launch_bounds__(256, 2)
gemm_mma(const __nv_bfloat16* __restrict__ a_hi,
         const __nv_bfloat16* __restrict__ a_lo,
         const __nv_bfloat16* __restrict__ b_hi,
         const __nv_bfloat16* __restrict__ b_lo,
         const float* __restrict__ bias,
         float* __restrict__ C,
         int Nc, int K)
{
    extern __shared__ __nv_bfloat16 sm[];
    __nv_bfloat16* Ah = sm;
    __nv_bfloat16* Al = Ah + TILE_ELEMS;
    __nv_bfloat16* Bh = Al + TILE_ELEMS;
    __nv_bfloat16* Bl = Bh + TILE_ELEMS;

    const int tid  = threadIdx.x;
    const int wid  = tid >> 5;
    const int lane = tid & 31;
    const int wm   = wid >> 2;          // 0..1
    const int wn   = wid & 3;           // 0..3
    const int m0   = blockIdx.y * 128;
    const int n0   = blockIdx.x * 128;

    const int lr = lane >> 2;           // 0..7
    const int lc = (lane & 3) * 2;      // 0,2,4,6

    float acc[4][4][4];
#pragma unroll
    for (int i = 0; i < 4; i++)
#pragma unroll
        for (int j = 0; j < 4; j++)
#pragma unroll
            for (int q = 0; q < 4; q++) acc[i][j][q] = 0.f;

    const int nchunk = K >> 6;
    for (int c = 0; c < nchunk; c++) {
        const int k0 = c << 6;
        __syncthreads();
        load_tile(a_hi, m0, K, k0, Ah, tid);
        load_tile(a_lo, m0, K, k0, Al, tid);
        load_tile(b_hi, n0, K, k0, Bh, tid);
        load_tile(b_lo, n0, K, k0, Bl, tid);
        __syncthreads();

#pragma unroll
        for (int kk = 0; kk < 4; kk++) {
            const int kc = kk * 16 + lc;
            uint32_t bh[4][2], bl[4][2];
#pragma unroll
            for (int nf = 0; nf < 4; nf++) {
                int nrow = wn * 32 + nf * 8 + lr;
                bh[nf][0] = lds_u32(&Bh[nrow * AS_ + kc]);
                bh[nf][1] = lds_u32(&Bh[nrow * AS_ + kc + 8]);
                bl[nf][0] = lds_u32(&Bl[nrow * AS_ + kc]);
                bl[nf][1] = lds_u32(&Bl[nrow * AS_ + kc + 8]);
            }
#pragma unroll
            for (int mf = 0; mf < 4; mf++) {
                int r0 = wm * 64 + mf * 16 + lr;
                uint32_t ah[4], al[4];
                ah[0] = lds_u32(&Ah[r0 * AS_ + kc]);
                ah[1] = lds_u32(&Ah[(r0 + 8) * AS_ + kc]);
                ah[2] = lds_u32(&Ah[r0 * AS_ + kc + 8]);
                ah[3] = lds_u32(&Ah[(r0 + 8) * AS_ + kc + 8]);
                al[0] = lds_u32(&Al[r0 * AS_ + kc]);
                al[1] = lds_u32(&Al[(r0 + 8) * AS_ + kc]);
                al[2] = lds_u32(&Al[r0 * AS_ + kc + 8]);
                al[3] = lds_u32(&Al[(r0 + 8) * AS_ + kc + 8]);
#pragma unroll
                for (int nf = 0; nf < 4; nf++) {
                    mma16816(acc[mf][nf], ah, bh[nf]);
                    mma16816(acc[mf][nf], ah, bl[nf]);
                    mma16816(acc[mf][nf], al, bh[nf]);
                }
            }
        }
    }

    // Epilogue: accum thread layout: rows lr(+8), cols lc(+1)
#pragma unroll
    for (int mf = 0; mf < 4; mf++) {
#pragma unroll
        for (int nf = 0; nf < 4; nf++) {
            int row = m0 + wm * 64 + mf * 16 + lr;
            int col = n0 + wn * 32 + nf * 8 + lc;
            float b0 = __ldg(&bias[col]), b1 = __ldg(&bias[col + 1]);
            float2 v0 = {acc[mf][nf][0] + b0, acc[mf][nf][1] + b1};
            float2 v1 = {acc[mf][nf][2] + b0, acc[mf][nf][3] + b1};
            *reinterpret_cast<float2*>(&C[(size_t)row * Nc + col]) = v0;
            *reinterpret_cast<float2*>(&C[(size_t)(row + 8) * Nc + col]) = v1;
        }
    }
}

// ---------------------------------------------------------------------------
// Fused flash-style attention (unchanged FFMA path; mma.sync port next round)
// ---------------------------------------------------------------------------
#define LDS_ 65

__global__ void __launch_bounds__(256)
attn_kernel(const float* __restrict__ qkv, float* __restrict__ attn_out)
{
    extern __shared__ float smf[];
    float* Qs  = smf;
    float* KVs = smf + 64 * LDS_;
    float* Ss  = smf + 2 * 64 * LDS_;

    const int tx = threadIdx.x, ty = threadIdx.y;
    const int tid = ty * 16 + tx;
    const int q0 = blockIdx.x * 64;
    const int h = blockIdx.y, b = blockIdx.z;
    const float scale = 0.125f;
    const size_t base = (size_t)b * N_ * THREE_E;
    const int hoff = h * D_;

    for (int i = tid; i < 64 * 64; i += 256) {
        int r = i >> 6, c = i & 63;
        Qs[r * LDS_ + c] = qkv[base + (size_t)(q0 + r) * THREE_E + hoff + c];
    }

    float o[4][4], m_r[4], l_r[4];
#pragma unroll
    for (int i = 0; i < 4; i++) {
        m_r[i] = -1e30f; l_r[i] = 0.f;
#pragma unroll
        for (int j = 0; j < 4; j++) o[i][j] = 0.f;
    }

    for (int kt = 0; kt < N_ / 64; kt++) {
        const int k0 = kt * 64;
        __syncthreads();
        for (int i = tid; i < 64 * 64; i += 256) {
            int r = i >> 6, c = i & 63;
            KVs[r * LDS_ + c] = qkv[base + (size_t)(k0 + r) * THREE_E + E_ + hoff + c];
        }
        __syncthreads();

        float s[4][4];
#pragma unroll
        for (int i = 0; i < 4; i++)
#pragma unroll
            for (int j = 0; j < 4; j++) s[i][j] = 0.f;
#pragma unroll 4
        for (int d = 0; d < 64; d++) {
            float a[4], bb[4];
#pragma unroll
            for (int i = 0; i < 4; i++) a[i]  = Qs[(ty * 4 + i) * LDS_ + d];
#pragma unroll
            for (int j = 0; j < 4; j++) bb[j] = KVs[(tx * 4 + j) * LDS_ + d];
#pragma unroll
            for (int i = 0; i < 4; i++)
#pragma unroll
                for (int j = 0; j < 4; j++)
                    s[i][j] = fmaf(a[i], bb[j], s[i][j]);
        }

#pragma unroll
        for (int i = 0; i < 4; i++) {
            float rmax = -1e30f;
#pragma unroll
            for (int j = 0; j < 4; j++) { s[i][j] *= scale; rmax = fmaxf(rmax, s[i][j]); }
#pragma unroll
            for (int off = 8; off > 0; off >>= 1)
                rmax = fmaxf(rmax, __shfl_xor_sync(0xffffffffu, rmax, off, 16));
            float newm = fmaxf(m_r[i], rmax);
            float alpha = __expf(m_r[i] - newm);
            m_r[i] = newm;
            float rsum = 0.f;
#pragma unroll
            for (int j = 0; j < 4; j++) { s[i][j] = __expf(s[i][j] - newm); rsum += s[i][j]; }
#pragma unroll
            for (int off = 8; off > 0; off >>= 1)
                rsum += __shfl_xor_sync(0xffffffffu, rsum, off, 16);
            l_r[i] = l_r[i] * alpha + rsum;
#pragma unroll
            for (int j = 0; j < 4; j++) o[i][j] *= alpha;
        }
        __syncthreads();

#pragma unroll
        for (int i = 0; i < 4; i++)
#pragma unroll
            for (int j = 0; j < 4; j++)
                Ss[(ty * 4 + i) * LDS_ + tx * 4 + j] = s[i][j];
        for (int i = tid; i < 64 * 64; i += 256) {
            int r = i >> 6, c = i & 63;
            KVs[r * LDS_ + c] = qkv[base + (size_t)(k0 + r) * THREE_E + 2 * E_ + hoff + c];
        }
        __syncthreads();

#pragma unroll 4
        for (int kk = 0; kk < 64; kk++) {
            float a[4], bb[4];
#pragma unroll
            for (int i = 0; i < 4; i++) a[i]  = Ss[(ty * 4 + i) * LDS_ + kk];
#pragma unroll
            for (int j = 0; j < 4; j++) bb[j] = KVs[kk * LDS_ + tx * 4 + j];
#pragma unroll
            for (int i = 0; i < 4; i++)
#pragma unroll
                for (int j = 0; j < 4; j++)
                    o[i][j] = fmaf(a[i], bb[j], o[i][j]);
        }
    }

#pragma unroll
    for (int i = 0; i < 4; i++) {
        float inv_l = 1.0f / l_r[i];
        size_t row = ((size_t)b * N_ + q0 + ty * 4 + i) * E_ + hoff + tx * 4;
#pragma unroll
        for (int j = 0; j < 4; j++)
            attn_out[row + j] = o[i][j] * inv_l;
    }
}

// ---------------------------------------------------------------------------
extern "C" void kernel_launch(void* const* d_in, const int* in_sizes, int n_in,
                              void* d_out, int out_size)
{
    const float* x      = (const float*)d_in[0];
    const float* w_qkv  = (const float*)d_in[1];
    const float* b_qkv  = (const float*)d_in[2];
    const float* w_proj = (const float*)d_in[3];
    const float* b_proj = (const float*)d_in[4];
    float* out = (float*)d_out;

    float *qkv_p, *attn_p;
    __nv_bfloat16 *ah, *al, *wqh, *wql, *wph, *wpl;
    cudaGetSymbolAddress((void**)&qkv_p, g_qkv);
    cudaGetSymbolAddress((void**)&attn_p, g_attn);
    cudaGetSymbolAddress((void**)&ah,  g_a_hi);
    cudaGetSymbolAddress((void**)&al,  g_a_lo);
    cudaGetSymbolAddress((void**)&wqh, g_wq_hi);
    cudaGetSymbolAddress((void**)&wql, g_wq_lo);
    cudaGetSymbolAddress((void**)&wph, g_wp_hi);
    cudaGetSymbolAddress((void**)&wpl, g_wp_lo);

    const int attn_smem = 3 * 64 * LDS_ * (int)sizeof(float);
    static bool attr_set = false;
    if (!attr_set) {
        cudaFuncSetAttribute(attn_kernel,
                             cudaFuncAttributeMaxDynamicSharedMemorySize, attn_smem);
        cudaFuncSetAttribute(gemm_mma,
                             cudaFuncAttributeMaxDynamicSharedMemorySize, GEMM_SMEM);
        attr_set = true;
    }

    // Prep: split x, transpose+split weights
    {
        int n = M_ROWS * E_;
        split_f32<<<(n + 255) / 256, 256>>>(x, ah, al, n);
    }
    transpose_split<<<dim3(THREE_E / 32, E_ / 32), dim3(32, 8)>>>(w_qkv, wqh, wql, E_, THREE_E);
    transpose_split<<<dim3(E_ / 32, E_ / 32), dim3(32, 8)>>>(w_proj, wph, wpl, E_, E_);

    // 1) QKV = x @ w_qkv + b_qkv   (split-bf16 tensor cores)
    gemm_mma<<<dim3(THREE_E / 128, M_ROWS / 128), 256, GEMM_SMEM>>>(
        ah, al, wqh, wql, b_qkv, qkv_p, THREE_E, E_);

    // 2) Fused attention -> g_attn
    attn_kernel<<<dim3(N_ / 64, H_, B_), dim3(16, 16), attn_smem>>>(qkv_p, attn_p);

    // 3) out = attn @ w_proj + b_proj
    {
        int n = M_ROWS * E_;
        split_f32<<<(n + 255) / 256, 256>>>(attn_p, ah, al, n);
    }
    gemm_mma<<<dim3(E_ / 128, M_ROWS / 128), 256, GEMM_SMEM>>>(
        ah, al, wph, wpl, b_proj, out, E_, E_);
}

// round 5
// speedup vs baseline: 2.9901x; 2.2664x over previous
#include <cuda_runtime.h>
#include <cuda_bf16.h>
#include <cstdint>
#include <math.h>

#define B_ 2
#define N_ 2048
#define E_ 1024
#define H_ 16
#define D_ 64
#define THREE_E 3072
#define M_ROWS 4096   // B*N

// ---------------------------------------------------------------------------
// Scratch (__device__ globals; allocation-free rule)
// ---------------------------------------------------------------------------
__device__ __nv_bfloat16 g_a_hi[(size_t)M_ROWS * E_];        // x split, then attn-out split
__device__ __nv_bfloat16 g_a_lo[(size_t)M_ROWS * E_];
__device__ __nv_bfloat16 g_qkv_hi[(size_t)M_ROWS * THREE_E]; // qkv split (gemm1 out)
__device__ __nv_bfloat16 g_qkv_lo[(size_t)M_ROWS * THREE_E];
__device__ __nv_bfloat16 g_wq_hi[(size_t)THREE_E * E_];      // w_qkv^T [Nc,K]
__device__ __nv_bfloat16 g_wq_lo[(size_t)THREE_E * E_];
__device__ __nv_bfloat16 g_wp_hi[(size_t)E_ * E_];           // w_proj^T
__device__ __nv_bfloat16 g_wp_lo[(size_t)E_ * E_];

// ---------------------------------------------------------------------------
// Warp-level bf16 MMA (sm_80+, valid on plain compute_100)
// ---------------------------------------------------------------------------
__device__ __forceinline__ void mma16816(float* c, const uint32_t* a, const uint32_t* b) {
    asm volatile(
        "mma.sync.aligned.m16n8k16.row.col.f32.bf16.bf16.f32 "
        "{%0,%1,%2,%3}, {%4,%5,%6,%7}, {%8,%9}, {%0,%1,%2,%3};"
        : "+f"(c[0]), "+f"(c[1]), "+f"(c[2]), "+f"(c[3])
        : "r"(a[0]), "r"(a[1]), "r"(a[2]), "r"(a[3]), "r"(b[0]), "r"(b[1]));
}
__device__ __forceinline__ uint32_t lds_u32(const __nv_bfloat16* p) {
    return *reinterpret_cast<const uint32_t*>(p);
}
__device__ __forceinline__ void ldmx4_trans(uint32_t* r, uint32_t addr) {
    asm volatile("ldmatrix.sync.aligned.m8n8.x4.trans.shared.b16 {%0,%1,%2,%3}, [%4];"
                 : "=r"(r[0]), "=r"(r[1]), "=r"(r[2]), "=r"(r[3]) : "r"(addr));
}
__device__ __forceinline__ uint32_t smem_u32(const void* p) {
    uint32_t a;
    asm("{ .reg .u64 t; cvta.to.shared.u64 t, %1; cvt.u32.u64 %0, t; }"
        : "=r"(a) : "l"(p));
    return a;
}
__device__ __forceinline__ uint32_t pack_bf16(float a, float b) {
    __nv_bfloat162 v = __floats2bfloat162_rn(a, b);   // .x = a (low), .y = b (high)
    return *reinterpret_cast<uint32_t*>(&v);
}

// ---------------------------------------------------------------------------
// Prep kernels
// ---------------------------------------------------------------------------
__global__ void split_f32(const float* __restrict__ src,
                          __nv_bfloat16* __restrict__ hi,
                          __nv_bfloat16* __restrict__ lo, int n)
{
    int i = blockIdx.x * blockDim.x + threadIdx.x;
    if (i < n) {
        float x = src[i];
        __nv_bfloat16 h = __float2bfloat16(x);
        hi[i] = h;
        lo[i] = __float2bfloat16(x - __bfloat162float(h));
    }
}

__global__ void transpose_split(const float* __restrict__ w,
                                __nv_bfloat16* __restrict__ thi,
                                __nv_bfloat16* __restrict__ tlo,
                                int K, int Nc)
{
    __shared__ float t[32][33];
    int n0 = blockIdx.x * 32, k0 = blockIdx.y * 32;
    int tx = threadIdx.x, ty = threadIdx.y;     // 32 x 8
#pragma unroll
    for (int i = 0; i < 32; i += 8)
        t[ty + i][tx] = w[(size_t)(k0 + ty + i) * Nc + n0 + tx];
    __syncthreads();
#pragma unroll
    for (int i = 0; i < 32; i += 8) {
        float v = t[tx][ty + i];
        __nv_bfloat16 h = __float2bfloat16(v);
        size_t o = (size_t)(n0 + ty + i) * K + k0 + tx;
        thi[o] = h;
        tlo[o] = __float2bfloat16(v - __bfloat162float(h));
    }
}

// ---------------------------------------------------------------------------
// Split-bf16 GEMM (proven R4): C = A @ Wt^T + bias.
// Optionally writes split bf16 hi/lo output instead of fp32.
// ---------------------------------------------------------------------------
#define AS_ 72
#define TILE_ELEMS (128 * AS_)
#define GEMM_SMEM (4 * TILE_ELEMS * 2)   // 73728 B

__device__ __forceinline__ void load_tile(const __nv_bfloat16* __restrict__ src,
                                          int row0, int K, int k0,
                                          __nv_bfloat16* dst, int tid)
{
#pragma unroll
    for (int it = 0; it < 4; it++) {
        int idx = tid + it * 256;
        int r = idx >> 3, g = idx & 7;
        uint4 v = *reinterpret_cast<const uint4*>(
            src + (size_t)(row0 + r) * K + k0 + g * 8);
        *reinterpret_cast<uint4*>(dst + r * AS_ + g * 8) = v;
    }
}

__global__ void __launch_bounds__(256, 2)
gemm_mma(const __nv_bfloat16* __restrict__ a_hi,
         const __nv_bfloat16* __restrict__ a_lo,
         const __nv_bfloat16* __restrict__ b_hi,
         const __nv_bfloat16* __restrict__ b_lo,
         const float* __restrict__ bias,
         float* __restrict__ C,
         __nv_bfloat16* __restrict__ Chi,
         __nv_bfloat16* __restrict__ Clo,
         int Nc, int K, int split_out)
{
    extern __shared__ __nv_bfloat16 sm[];
    __nv_bfloat16* Ah = sm;
    __nv_bfloat16* Al = Ah + TILE_ELEMS;
    __nv_bfloat16* Bh = Al + TILE_ELEMS;
    __nv_bfloat16* Bl = Bh + TILE_ELEMS;

    const int tid  = threadIdx.x;
    const int wid  = tid >> 5;
    const int lane = tid & 31;
    const int wm   = wid >> 2;
    const int wn   = wid & 3;
    const int m0   = blockIdx.y * 128;
    const int n0   = blockIdx.x * 128;
    const int lr = lane >> 2;
    const int lc = (lane & 3) * 2;

    float acc[4][4][4];
#pragma unroll
    for (int i = 0; i < 4; i++)
#pragma unroll
        for (int j = 0; j < 4; j++)
#pragma unroll
            for (int q = 0; q < 4; q++) acc[i][j][q] = 0.f;

    const int nchunk = K >> 6;
    for (int c = 0; c < nchunk; c++) {
        const int k0 = c << 6;
        __syncthreads();
        load_tile(a_hi, m0, K, k0, Ah, tid);
        load_tile(a_lo, m0, K, k0, Al, tid);
        load_tile(b_hi, n0, K, k0, Bh, tid);
        load_tile(b_lo, n0, K, k0, Bl, tid);
        __syncthreads();

#pragma unroll
        for (int kk = 0; kk < 4; kk++) {
            const int kc = kk * 16 + lc;
            uint32_t bh[4][2], bl[4][2];
#pragma unroll
            for (int nf = 0; nf < 4; nf++) {
                int nrow = wn * 32 + nf * 8 + lr;
                bh[nf][0] = lds_u32(&Bh[nrow * AS_ + kc]);
                bh[nf][1] = lds_u32(&Bh[nrow * AS_ + kc + 8]);
                bl[nf][0] = lds_u32(&Bl[nrow * AS_ + kc]);
                bl[nf][1] = lds_u32(&Bl[nrow * AS_ + kc + 8]);
            }
#pragma unroll
            for (int mf = 0; mf < 4; mf++) {
                int r0 = wm * 64 + mf * 16 + lr;
                uint32_t ah[4], al[4];
                ah[0] = lds_u32(&Ah[r0 * AS_ + kc]);
                ah[1] = lds_u32(&Ah[(r0 + 8) * AS_ + kc]);
                ah[2] = lds_u32(&Ah[r0 * AS_ + kc + 8]);
                ah[3] = lds_u32(&Ah[(r0 + 8) * AS_ + kc + 8]);
                al[0] = lds_u32(&Al[r0 * AS_ + kc]);
                al[1] = lds_u32(&Al[(r0 + 8) * AS_ + kc]);
                al[2] = lds_u32(&Al[r0 * AS_ + kc + 8]);
                al[3] = lds_u32(&Al[(r0 + 8) * AS_ + kc + 8]);
#pragma unroll
                for (int nf = 0; nf < 4; nf++) {
                    mma16816(acc[mf][nf], ah, bh[nf]);
                    mma16816(acc[mf][nf], ah, bl[nf]);
                    mma16816(acc[mf][nf], al, bh[nf]);
                }
            }
        }
    }

#pragma unroll
    for (int mf = 0; mf < 4; mf++) {
#pragma unroll
        for (int nf = 0; nf < 4; nf++) {
            int row = m0 + wm * 64 + mf * 16 + lr;
            int col = n0 + wn * 32 + nf * 8 + lc;
            float b0 = __ldg(&bias[col]), b1 = __ldg(&bias[col + 1]);
            float v0 = acc[mf][nf][0] + b0, v1 = acc[mf][nf][1] + b1;
            float v2 = acc[mf][nf][2] + b0, v3 = acc[mf][nf][3] + b1;
            if (!split_out) {
                float2 p0 = {v0, v1}, p1 = {v2, v3};
                *reinterpret_cast<float2*>(&C[(size_t)row * Nc + col]) = p0;
                *reinterpret_cast<float2*>(&C[(size_t)(row + 8) * Nc + col]) = p1;
            } else {
                __nv_bfloat16 h0 = __float2bfloat16(v0), h1 = __float2bfloat16(v1);
                __nv_bfloat16 h2 = __float2bfloat16(v2), h3 = __float2bfloat16(v3);
                float l0 = v0 - __bfloat162float(h0), l1 = v1 - __bfloat162float(h1);
                float l2 = v2 - __bfloat162float(h2), l3 = v3 - __bfloat162float(h3);
                size_t o0 = (size_t)row * Nc + col, o1 = (size_t)(row + 8) * Nc + col;
                *reinterpret_cast<uint32_t*>(&Chi[o0]) = pack_bf16(__bfloat162float(h0), __bfloat162float(h1));
                *reinterpret_cast<uint32_t*>(&Chi[o1]) = pack_bf16(__bfloat162float(h2), __bfloat162float(h3));
                *reinterpret_cast<uint32_t*>(&Clo[o0]) = pack_bf16(l0, l1);
                *reinterpret_cast<uint32_t*>(&Clo[o1]) = pack_bf16(l2, l3);
            }
        }
    }
}

// ---------------------------------------------------------------------------
// Tensor-core flash attention.
// CTA: 64 q-rows, 4 warps (16 rows each), 128 threads. 64-key chunks.
// S = Q K^T via split-bf16 (3 mma); online softmax; O += P V via split-P /
// split-V (3 mma), V frags via ldmatrix.trans.
// ---------------------------------------------------------------------------
#define TAS 72
#define ATT_TILE (64 * TAS)                 // elems per tile
#define ATT_SMEM (6 * ATT_TILE * 2)         // 55296 B

__device__ __forceinline__ void ld_att_tile(const __nv_bfloat16* __restrict__ g,
                                            int n0, int coloff,
                                            __nv_bfloat16* dst, int tid)
{
#pragma unroll
    for (int it = 0; it < 4; it++) {
        int idx = tid + it * 128;            // 0..511
        int r = idx >> 3, gq = idx & 7;      // 64 rows x 8 groups
        uint4 v = *reinterpret_cast<const uint4*>(
            g + (size_t)(n0 + r) * THREE_E + coloff + gq * 8);
        *reinterpret_cast<uint4*>(dst + r * TAS + gq * 8) = v;
    }
}

__global__ void __launch_bounds__(128)
attn_mma(const __nv_bfloat16* __restrict__ qkvh,
         const __nv_bfloat16* __restrict__ qkvl,
         __nv_bfloat16* __restrict__ out_hi,
         __nv_bfloat16* __restrict__ out_lo)
{
    extern __shared__ __nv_bfloat16 smb[];
    __nv_bfloat16* Qh = smb;
    __nv_bfloat16* Ql = Qh + ATT_TILE;
    __nv_bfloat16* Kh = Ql + ATT_TILE;
    __nv_bfloat16* Kl = Kh + ATT_TILE;
    __nv_bfloat16* Vh = Kl + ATT_TILE;
    __nv_bfloat16* Vl = Vh + ATT_TILE;

    const int tid  = threadIdx.x;
    const int wid  = tid >> 5;
    const int lane = tid & 31;
    const int lr = lane >> 2;
    const int lc = (lane & 3) * 2;
    const int q0 = blockIdx.x * 64;
    const int h  = blockIdx.y;
    const int b  = blockIdx.z;
    const int hoff = h * D_;
    const int nbase = b * N_;

    // Load Q tile (split) and build persistent Q fragments
    ld_att_tile(qkvh, nbase + q0, hoff, Qh, tid);
    ld_att_tile(qkvl, nbase + q0, hoff, Ql, tid);
    __syncthreads();

    uint32_t qh[4][4], ql[4][4];
    const int qrow = wid * 16 + lr;
#pragma unroll
    for (int kc = 0; kc < 4; kc++) {
        int c0 = kc * 16 + lc;
        qh[kc][0] = lds_u32(&Qh[qrow * TAS + c0]);
        qh[kc][1] = lds_u32(&Qh[(qrow + 8) * TAS + c0]);
        qh[kc][2] = lds_u32(&Qh[qrow * TAS + c0 + 8]);
        qh[kc][3] = lds_u32(&Qh[(qrow + 8) * TAS + c0 + 8]);
        ql[kc][0] = lds_u32(&Ql[qrow * TAS + c0]);
        ql[kc][1] = lds_u32(&Ql[(qrow + 8) * TAS + c0]);
        ql[kc][2] = lds_u32(&Ql[qrow * TAS + c0 + 8]);
        ql[kc][3] = lds_u32(&Ql[(qrow + 8) * TAS + c0 + 8]);
    }

    float o[32];
#pragma unroll
    for (int i = 0; i < 32; i++) o[i] = 0.f;
    float m0 = -1e30f, m1 = -1e30f, l0 = 0.f, l1 = 0.f;

    const uint32_t vh_base = smem_u32(Vh);
    const uint32_t vl_base = smem_u32(Vl);
    // ldmatrix lane address components (within a 16x16 sub-tile)
    const int lgrp = lane >> 3;             // 0..3
    const int lrow = lane & 7;
    const int key_in = lrow + 8 * (lgrp & 1);
    const int d_in   = 8 * (lgrp >> 1);

    for (int kt = 0; kt < N_ / 64; kt++) {
        const int k0 = kt * 64;
        __syncthreads();
        ld_att_tile(qkvh, nbase + k0, E_ + hoff, Kh, tid);
        ld_att_tile(qkvl, nbase + k0, E_ + hoff, Kl, tid);
        ld_att_tile(qkvh, nbase + k0, 2 * E_ + hoff, Vh, tid);
        ld_att_tile(qkvl, nbase + k0, 2 * E_ + hoff, Vl, tid);
        __syncthreads();

        // Stage 1: S = Q K^T (split-bf16)
        float s[32];
#pragma unroll
        for (int i = 0; i < 32; i++) s[i] = 0.f;
#pragma unroll
        for (int kc = 0; kc < 4; kc++) {
            const int c0 = kc * 16 + lc;
            uint32_t kh[8][2], kl[8][2];
#pragma unroll
            for (int nf = 0; nf < 8; nf++) {
                int nrow = nf * 8 + lr;
                kh[nf][0] = lds_u32(&Kh[nrow * TAS + c0]);
                kh[nf][1] = lds_u32(&Kh[nrow * TAS + c0 + 8]);
                kl[nf][0] = lds_u32(&Kl[nrow * TAS + c0]);
                kl[nf][1] = lds_u32(&Kl[nrow * TAS + c0 + 8]);
            }
#pragma unroll
            for (int nf = 0; nf < 8; nf++) {
                mma16816(&s[nf * 4], qh[kc], kh[nf]);
                mma16816(&s[nf * 4], qh[kc], kl[nf]);
                mma16816(&s[nf * 4], ql[kc], kh[nf]);
            }
        }

        // Online softmax (rows lr and lr+8; reduce over 4-lane groups)
#pragma unroll
        for (int i = 0; i < 32; i++) s[i] *= 0.125f;
        float r0 = -1e30f, r1 = -1e30f;
#pragma unroll
        for (int nf = 0; nf < 8; nf++) {
            r0 = fmaxf(r0, fmaxf(s[nf * 4 + 0], s[nf * 4 + 1]));
            r1 = fmaxf(r1, fmaxf(s[nf * 4 + 2], s[nf * 4 + 3]));
        }
        r0 = fmaxf(r0, __shfl_xor_sync(0xffffffffu, r0, 1));
        r0 = fmaxf(r0, __shfl_xor_sync(0xffffffffu, r0, 2));
        r1 = fmaxf(r1, __shfl_xor_sync(0xffffffffu, r1, 1));
        r1 = fmaxf(r1, __shfl_xor_sync(0xffffffffu, r1, 2));

        float nm0 = fmaxf(m0, r0), nm1 = fmaxf(m1, r1);
        float a0 = __expf(m0 - nm0), a1 = __expf(m1 - nm1);
        m0 = nm0; m1 = nm1;

        float sum0 = 0.f, sum1 = 0.f;
#pragma unroll
        for (int nf = 0; nf < 8; nf++) {
            s[nf * 4 + 0] = __expf(s[nf * 4 + 0] - m0);
            s[nf * 4 + 1] = __expf(s[nf * 4 + 1] - m0);
            s[nf * 4 + 2] = __expf(s[nf * 4 + 2] - m1);
            s[nf * 4 + 3] = __expf(s[nf * 4 + 3] - m1);
            sum0 += s[nf * 4 + 0] + s[nf * 4 + 1];
            sum1 += s[nf * 4 + 2] + s[nf * 4 + 3];
        }
        sum0 += __shfl_xor_sync(0xffffffffu, sum0, 1);
        sum0 += __shfl_xor_sync(0xffffffffu, sum0, 2);
        sum1 += __shfl_xor_sync(0xffffffffu, sum1, 1);
        sum1 += __shfl_xor_sync(0xffffffffu, sum1, 2);
        l0 = l0 * a0 + sum0;
        l1 = l1 * a1 + sum1;
#pragma unroll
        for (int nf = 0; nf < 8; nf++) {
            o[nf * 4 + 0] *= a0; o[nf * 4 + 1] *= a0;
            o[nf * 4 + 2] *= a1; o[nf * 4 + 3] *= a1;
        }

        // Split P into bf16 hi/lo fragments (C-frag layout == A-frag layout)
        uint32_t pha[8], phb[8], pla[8], plb[8];
#pragma unroll
        for (int nf = 0; nf < 8; nf++) {
            float v0 = s[nf * 4 + 0], v1 = s[nf * 4 + 1];
            float v2 = s[nf * 4 + 2], v3 = s[nf * 4 + 3];
            __nv_bfloat16 h0 = __float2bfloat16(v0), h1 = __float2bfloat16(v1);
            __nv_bfloat16 h2 = __float2bfloat16(v2), h3 = __float2bfloat16(v3);
            pha[nf] = pack_bf16(__bfloat162float(h0), __bfloat162float(h1));
            phb[nf] = pack_bf16(__bfloat162float(h2), __bfloat162float(h3));
            pla[nf] = pack_bf16(v0 - __bfloat162float(h0), v1 - __bfloat162float(h1));
            plb[nf] = pack_bf16(v2 - __bfloat162float(h2), v3 - __bfloat162float(h3));
        }

        // Stage 2: O += P V (split-P x split-V), V frags via ldmatrix.trans
#pragma unroll
        for (int t = 0; t < 4; t++) {
            uint32_t ah[4] = {pha[2 * t], phb[2 * t], pha[2 * t + 1], phb[2 * t + 1]};
            uint32_t al[4] = {pla[2 * t], plb[2 * t], pla[2 * t + 1], plb[2 * t + 1]};
            const int keyr = t * 16 + key_in;
#pragma unroll
            for (int dp = 0; dp < 4; dp++) {
                const uint32_t off = (uint32_t)(keyr * TAS + dp * 16 + d_in) * 2;
                uint32_t vh[4], vl[4];
                ldmx4_trans(vh, vh_base + off);
                ldmx4_trans(vl, vl_base + off);
                mma16816(&o[(2 * dp) * 4], ah, &vh[0]);
                mma16816(&o[(2 * dp) * 4], ah, &vl[0]);
                mma16816(&o[(2 * dp) * 4], al, &vh[0]);
                mma16816(&o[(2 * dp + 1) * 4], ah, &vh[2]);
                mma16816(&o[(2 * dp + 1) * 4], ah, &vl[2]);
                mma16816(&o[(2 * dp + 1) * 4], al, &vh[2]);
            }
        }
    }

    // Epilogue: normalize, split to bf16 hi/lo, write [B,N,E]
    const float inv0 = 1.f / l0, inv1 = 1.f / l1;
#pragma unroll
    for (int nf = 0; nf < 8; nf++) {
        float v0 = o[nf * 4 + 0] * inv0, v1 = o[nf * 4 + 1] * inv0;
        float v2 = o[nf * 4 + 2] * inv1, v3 = o[nf * 4 + 3] * inv1;
        size_t i0 = (size_t)(nbase + q0 + qrow) * E_ + hoff + nf * 8 + lc;
        size_t i1 = (size_t)(nbase + q0 + qrow + 8) * E_ + hoff + nf * 8 + lc;
        __nv_bfloat16 h0 = __float2bfloat16(v0), h1 = __float2bfloat16(v1);
        __nv_bfloat16 h2 = __float2bfloat16(v2), h3 = __float2bfloat16(v3);
        *reinterpret_cast<uint32_t*>(&out_hi[i0]) = pack_bf16(__bfloat162float(h0), __bfloat162float(h1));
        *reinterpret_cast<uint32_t*>(&out_hi[i1]) = pack_bf16(__bfloat162float(h2), __bfloat162float(h3));
        *reinterpret_cast<uint32_t*>(&out_lo[i0]) = pack_bf16(v0 - __bfloat162float(h0), v1 - __bfloat162float(h1));
        *reinterpret_cast<uint32_t*>(&out_lo[i1]) = pack_bf16(v2 - __bfloat162float(h2), v3 - __bfloat162float(h3));
    }
}

// ---------------------------------------------------------------------------
extern "C" void kernel_launch(void* const* d_in, const int* in_sizes, int n_in,
                              void* d_out, int out_size)
{
    const float* x      = (const float*)d_in[0];
    const float* w_qkv  = (const float*)d_in[1];
    const float* b_qkv  = (const float*)d_in[2];
    const float* w_proj = (const float*)d_in[3];
    const float* b_proj = (const float*)d_in[4];
    float* out = (float*)d_out;

    __nv_bfloat16 *ah, *al, *qh, *qlp, *wqh, *wql, *wph, *wpl;
    cudaGetSymbolAddress((void**)&ah,  g_a_hi);
    cudaGetSymbolAddress((void**)&al,  g_a_lo);
    cudaGetSymbolAddress((void**)&qh,  g_qkv_hi);
    cudaGetSymbolAddress((void**)&qlp, g_qkv_lo);
    cudaGetSymbolAddress((void**)&wqh, g_wq_hi);
    cudaGetSymbolAddress((void**)&wql, g_wq_lo);
    cudaGetSymbolAddress((void**)&wph, g_wp_hi);
    cudaGetSymbolAddress((void**)&wpl, g_wp_lo);

    static bool attr_set = false;
    if (!attr_set) {
        cudaFuncSetAttribute(gemm_mma,
                             cudaFuncAttributeMaxDynamicSharedMemorySize, GEMM_SMEM);
        cudaFuncSetAttribute(attn_mma,
                             cudaFuncAttributeMaxDynamicSharedMemorySize, ATT_SMEM);
        attr_set = true;
    }

    // Prep
    {
        int n = M_ROWS * E_;
        split_f32<<<(n + 255) / 256, 256>>>(x, ah, al, n);
    }
    transpose_split<<<dim3(THREE_E / 32, E_ / 32), dim3(32, 8)>>>(w_qkv, wqh, wql, E_, THREE_E);
    transpose_split<<<dim3(E_ / 32, E_ / 32), dim3(32, 8)>>>(w_proj, wph, wpl, E_, E_);

    // 1) QKV gemm, split-bf16 output
    gemm_mma<<<dim3(THREE_E / 128, M_ROWS / 128), 256, GEMM_SMEM>>>(
        ah, al, wqh, wql, b_qkv, nullptr, qh, qlp, THREE_E, E_, 1);

    // 2) Tensor-core flash attention -> split output into ah/al (x no longer needed)
    attn_mma<<<dim3(N_ / 64, H_, B_), 128, ATT_SMEM>>>(qh, qlp, ah, al);

    // 3) Projection gemm, fp32 output
    gemm_mma<<<dim3(E_ / 128, M_ROWS / 128), 256, GEMM_SMEM>>>(
        ah, al, wph, wpl, b_proj, out, nullptr, nullptr, E_, E_, 0);
}